// round 3
// baseline (speedup 1.0000x reference)
#include <cuda_runtime.h>

// AdaptiveFeaturePooling: 4-level ROIAlign (out=14, sr=2) + max over levels.
// Launch 1: cudaMemsetAsync zero-fill of the whole output (bulk of the bytes).
// Launch 2: per-ROI sparse kernel writing only cells with a live bilinear tap
//           (>95% of ROIs have none due to the cumulative scale blow-up).

#define OUTSZ  14
#define CELLS  196
#define CH     256
#define GSAMP  28           // OUTSZ*2

__global__ __launch_bounds__(256, 6)
void afp_sparse_kernel(const float* __restrict__ f0, const float* __restrict__ f1,
                       const float* __restrict__ f2, const float* __restrict__ f3,
                       const float* __restrict__ rois, float* __restrict__ out)
{
    __shared__ int   s_lo[4][2][GSAMP];
    __shared__ int   s_hi[4][2][GSAMP];
    __shared__ float s_w0[4][2][GSAMP];
    __shared__ float s_w1[4][2][GSAMP];
    __shared__ short s_vcell[CELLS];
    __shared__ unsigned char s_vmask[CELLS];
    __shared__ int s_nvalid;

    const int r   = blockIdx.x;
    const int tid = threadIdx.x;

    // ---- Phase A: bilinear prep, replicating reference fp32 op order exactly.
    if (tid < 4 * 2 * GSAMP) {
        int l   = tid / (2 * GSAMP);
        int rem = tid - l * (2 * GSAMP);
        int a   = rem / GSAMP;           // 0=y, 1=x
        int j   = rem - a * GSAMP;

        float p1 = rois[r * 4 + (a == 0 ? 1 : 0)];
        float p2 = rois[r * 4 + (a == 0 ? 3 : 2)];
        #pragma unroll
        for (int i = 3; i >= 0; --i) {
            if (i >= l) {
                float s = (float)(28 << i);
                p1 = __fmul_rn(p1, s);
                p2 = __fmul_rn(p2, s);
            }
        }
        float len  = fmaxf(__fadd_rn(p2, -p1), 1.0f);
        float t    = __fdiv_rn(len, 14.0f);
        float step = ((float)j + 0.5f) * 0.5f;
        float c    = __fadd_rn(p1, __fmul_rn(step, t));

        int L = 224 >> l;
        bool valid = (c >= -1.0f) && (c <= (float)L);
        c = fminf(fmaxf(c, 0.0f), (float)(L - 1));
        float lo   = floorf(c);
        float frac = __fadd_rn(c, -lo);
        int loi = (int)lo;
        int hii = loi + 1;
        if (loi >= L - 1) { loi = L - 1; hii = L - 1; frac = 0.0f; }
        float v = valid ? 1.0f : 0.0f;
        s_lo[l][a][j] = loi;
        s_hi[l][a][j] = hii;
        s_w0[l][a][j] = (1.0f - frac) * v;
        s_w1[l][a][j] = frac * v;
    }
    if (tid == 255) s_nvalid = 0;
    __syncthreads();

    // ---- Phase B: compact list of cells with any live level.
    if (tid < CELLS) {
        int py = tid / OUTSZ;
        int px = tid - py * OUTSZ;
        unsigned m = 0;
        #pragma unroll
        for (int l = 0; l < 4; ++l) {
            float wy = s_w0[l][0][2*py]   + s_w1[l][0][2*py]
                     + s_w0[l][0][2*py+1] + s_w1[l][0][2*py+1];
            float wx = s_w0[l][1][2*px]   + s_w1[l][1][2*px]
                     + s_w0[l][1][2*px+1] + s_w1[l][1][2*px+1];
            if (wy > 0.0f && wx > 0.0f) m |= (1u << l);
        }
        if (m) {
            int pos = atomicAdd(&s_nvalid, 1);
            s_vcell[pos] = (short)tid;
            s_vmask[pos] = (unsigned char)m;
        }
    }
    __syncthreads();

    const int nv = s_nvalid;
    if (nv == 0) return;

    const float* fl[4] = { f0, f1, f2, f3 };
    const size_t base = (size_t)r * (CH * CELLS);
    const int c = tid;                   // thread = channel

    for (int v = 0; v < nv; ++v) {
        int cell = s_vcell[v];
        unsigned m = s_vmask[v];
        int py = cell / OUTSZ;
        int px = cell - py * OUTSZ;
        int sy = 2 * py, sx = 2 * px;

        float best = 0.0f;
        #pragma unroll
        for (int l = 0; l < 4; ++l) {
            float val = 0.0f;
            if (m & (1u << l)) {
                int W = 224 >> l;
                const float* fc = fl[l] + (size_t)c * (W * W);
                float acc = 0.0f;
                #pragma unroll
                for (int dy = 0; dy < 2; ++dy) {
                    float wy0 = s_w0[l][0][sy + dy];
                    float wy1 = s_w1[l][0][sy + dy];
                    if (wy0 + wy1 > 0.0f) {
                        int y0 = s_lo[l][0][sy + dy];
                        int y1 = s_hi[l][0][sy + dy];
                        const float* row0 = fc + y0 * W;
                        const float* row1 = fc + y1 * W;
                        #pragma unroll
                        for (int dx = 0; dx < 2; ++dx) {
                            float wx0 = s_w0[l][1][sx + dx];
                            float wx1 = s_w1[l][1][sx + dx];
                            if (wx0 + wx1 > 0.0f) {
                                int x0 = s_lo[l][1][sx + dx];
                                int x1 = s_hi[l][1][sx + dx];
                                acc += wy0 * (wx0 * row0[x0] + wx1 * row0[x1])
                                     + wy1 * (wx0 * row1[x0] + wx1 * row1[x1]);
                            }
                        }
                    }
                }
                val = acc * 0.25f;
            }
            best = fmaxf(best, val);
        }
        out[base + (size_t)c * CELLS + cell] = best;
    }
}

extern "C" void kernel_launch(void* const* d_in, const int* in_sizes, int n_in,
                              void* d_out, int out_size)
{
    const float* f0   = (const float*)d_in[0];
    const float* f1   = (const float*)d_in[1];
    const float* f2   = (const float*)d_in[2];
    const float* f3   = (const float*)d_in[3];
    const float* rois = (const float*)d_in[4];
    int R = in_sizes[4] / 4;

    cudaMemsetAsync(d_out, 0, (size_t)out_size * sizeof(float));
    afp_sparse_kernel<<<R, 256>>>(f0, f1, f2, f3, rois, (float*)d_out);
}

// round 4
// speedup vs baseline: 3.2837x; 3.2837x over previous
#include <cuda_runtime.h>

// AdaptiveFeaturePooling: 4-level ROIAlign (out=14, sr=2) + max over levels.
// R3 post-mortem: serial per-block processing of valid cells created ~95us
// straggler blocks. R4: global worklist of (roi,cell,mask), processed one
// entry per block so the rare valid work spreads across the whole chip.
//
// Nodes: reset counter -> build tables+worklist -> memset(out) -> scatter compute.

#define OUTSZ  14
#define CELLS  196
#define CH     256
#define GSAMP  28           // OUTSZ*2
#define MAXROI 512
#define CGRID  2048

// tab[r][l][a][j] = {w0, w1, lo(bits), hi(bits)}
__device__ float4 g_tab[MAXROI][4][2][GSAMP];
__device__ unsigned g_work[MAXROI * CELLS];   // (r<<12) | (cell<<4) | mask
__device__ int g_count;

__global__ void afp_reset() { g_count = 0; }

__global__ __launch_bounds__(256)
void afp_build(const float* __restrict__ rois, int R)
{
    __shared__ float s_w0[4][2][GSAMP];
    __shared__ float s_w1[4][2][GSAMP];

    const int r   = blockIdx.x;
    const int tid = threadIdx.x;

    if (tid < 4 * 2 * GSAMP) {
        int l   = tid / (2 * GSAMP);
        int rem = tid - l * (2 * GSAMP);
        int a   = rem / GSAMP;           // 0=y, 1=x
        int j   = rem - a * GSAMP;

        float p1 = rois[r * 4 + (a == 0 ? 1 : 0)];
        float p2 = rois[r * 4 + (a == 0 ? 3 : 2)];
        #pragma unroll
        for (int i = 3; i >= 0; --i) {
            if (i >= l) {
                float s = (float)(28 << i);
                p1 = __fmul_rn(p1, s);
                p2 = __fmul_rn(p2, s);
            }
        }
        float len  = fmaxf(__fadd_rn(p2, -p1), 1.0f);
        float t    = __fdiv_rn(len, 14.0f);
        float step = ((float)j + 0.5f) * 0.5f;
        float c    = __fadd_rn(p1, __fmul_rn(step, t));

        int L = 224 >> l;
        bool valid = (c >= -1.0f) && (c <= (float)L);
        c = fminf(fmaxf(c, 0.0f), (float)(L - 1));
        float lo   = floorf(c);
        float frac = __fadd_rn(c, -lo);
        int loi = (int)lo;
        int hii = loi + 1;
        if (loi >= L - 1) { loi = L - 1; hii = L - 1; frac = 0.0f; }
        float v = valid ? 1.0f : 0.0f;
        float w0 = (1.0f - frac) * v;
        float w1 = frac * v;
        s_w0[l][a][j] = w0;
        s_w1[l][a][j] = w1;
        g_tab[r][l][a][j] = make_float4(w0, w1, __int_as_float(loi), __int_as_float(hii));
    }
    __syncthreads();

    if (tid < CELLS) {
        int py = tid / OUTSZ;
        int px = tid - py * OUTSZ;
        unsigned m = 0;
        #pragma unroll
        for (int l = 0; l < 4; ++l) {
            float wy = s_w0[l][0][2*py]   + s_w1[l][0][2*py]
                     + s_w0[l][0][2*py+1] + s_w1[l][0][2*py+1];
            float wx = s_w0[l][1][2*px]   + s_w1[l][1][2*px]
                     + s_w0[l][1][2*px+1] + s_w1[l][1][2*px+1];
            if (wy > 0.0f && wx > 0.0f) m |= (1u << l);
        }
        if (m) {
            int pos = atomicAdd(&g_count, 1);
            g_work[pos] = ((unsigned)r << 12) | ((unsigned)tid << 4) | m;
        }
    }
}

__global__ __launch_bounds__(256)
void afp_scatter(const float* __restrict__ f0, const float* __restrict__ f1,
                 const float* __restrict__ f2, const float* __restrict__ f3,
                 float* __restrict__ out)
{
    const int n = g_count;
    const int c = threadIdx.x;           // channel
    const float* fl[4] = { f0, f1, f2, f3 };

    for (int e = blockIdx.x; e < n; e += CGRID) {
        unsigned w = g_work[e];
        int r    = (int)(w >> 12);
        int cell = (int)((w >> 4) & 0xFF);
        unsigned m = w & 0xF;
        int py = cell / OUTSZ;
        int px = cell - py * OUTSZ;
        int sy = 2 * py, sx = 2 * px;

        float best = 0.0f;
        #pragma unroll
        for (int l = 0; l < 4; ++l) {
            if (m & (1u << l)) {
                int W = 224 >> l;
                const float* fc = fl[l] + (size_t)c * (W * W);
                float acc = 0.0f;
                #pragma unroll
                for (int dy = 0; dy < 2; ++dy) {
                    float4 ty = g_tab[r][l][0][sy + dy];     // broadcast
                    float wy0 = ty.x, wy1 = ty.y;
                    if (wy0 + wy1 > 0.0f) {
                        int y0 = __float_as_int(ty.z);
                        int y1 = __float_as_int(ty.w);
                        const float* row0 = fc + y0 * W;
                        const float* row1 = fc + y1 * W;
                        #pragma unroll
                        for (int dx = 0; dx < 2; ++dx) {
                            float4 tx = g_tab[r][l][1][sx + dx];
                            float wx0 = tx.x, wx1 = tx.y;
                            if (wx0 + wx1 > 0.0f) {
                                int x0 = __float_as_int(tx.z);
                                int x1 = __float_as_int(tx.w);
                                acc += wy0 * (wx0 * row0[x0] + wx1 * row0[x1])
                                     + wy1 * (wx0 * row1[x0] + wx1 * row1[x1]);
                            }
                        }
                    }
                }
                best = fmaxf(best, acc * 0.25f);
            }
        }
        out[(size_t)r * (CH * CELLS) + (size_t)c * CELLS + cell] = best;
    }
}

extern "C" void kernel_launch(void* const* d_in, const int* in_sizes, int n_in,
                              void* d_out, int out_size)
{
    const float* f0   = (const float*)d_in[0];
    const float* f1   = (const float*)d_in[1];
    const float* f2   = (const float*)d_in[2];
    const float* f3   = (const float*)d_in[3];
    const float* rois = (const float*)d_in[4];
    int R = in_sizes[4] / 4;

    afp_reset<<<1, 1>>>();
    afp_build<<<R, 256>>>(rois, R);
    cudaMemsetAsync(d_out, 0, (size_t)out_size * sizeof(float));
    afp_scatter<<<CGRID, 256>>>(f0, f1, f2, f3, (float*)d_out);
}